// round 1
// baseline (speedup 1.0000x reference)
#include <cuda_runtime.h>
#include <cuda_bf16.h>
#include <cstdint>

// KVDequantizer: Q4 nibble unpack + per-block (32 elems) scale/bias dequant.
// Inputs (metadata order):
//   0: k_packed  int32  [2, 131072, 16]   (value 0..255: low nibble, high nibble)
//   1: k_scale   f32    [2, 131072, 1]
//   2: k_bias    f32    [2, 131072, 1]
//   3: v_packed  int32  [2, 131072, 16]
//   4: v_scale   f32    [2, 131072, 1]
//   5: v_bias    f32    [2, 131072, 1]
//   6: batch_size (scalar, unused — shapes are static)
// Output: flat fp32 [ K_dequant (8388608) | V_dequant (8388608) ]
// (The reference's reshapes are views; memory order is the flat dequant order.)

static constexpr int BATCH      = 2;
static constexpr int N_BLOCKS   = 131072;
static constexpr int PACKED_PER_BLOCK = 16;                       // int32 per 32-elem block
static constexpr long long PACKED_PER_TENSOR =
    (long long)BATCH * N_BLOCKS * PACKED_PER_BLOCK;               // 4,194,304
static constexpr int NVEC = (int)(PACKED_PER_TENSOR / 4);         // int4 units: 1,048,576

__global__ __launch_bounds__(256)
void kv_dequant_kernel(const int4* __restrict__ kp,
                       const float* __restrict__ ks,
                       const float* __restrict__ kb,
                       const int4* __restrict__ vp,
                       const float* __restrict__ vs,
                       const float* __restrict__ vb,
                       float4* __restrict__ out)
{
    int i = blockIdx.x * blockDim.x + threadIdx.x;   // 0 .. 2*NVEC-1

    const int4*  src;
    const float* sp;
    const float* bp;
    float4*      dst;
    int j;
    if (i < NVEC) {            // K half
        j = i;
        src = kp; sp = ks; bp = kb;
        dst = out;
    } else {                   // V half
        j = i - NVEC;
        src = vp; sp = vs; bp = vb;
        dst = out + (long long)NVEC * 2;
    }

    int4  p = src[j];
    // Block index: each block = 16 packed ints = 4 int4 units.
    int   blk = j >> 2;
    float s = __ldg(sp + blk);
    float b = __ldg(bp + blk);

    // Each packed int32 (value 0..255): out[2m] = low nibble, out[2m+1] = high nibble.
    float4 o0, o1;
    o0.x = fmaf((float)(p.x & 15), s, b);
    o0.y = fmaf((float)(p.x >> 4), s, b);
    o0.z = fmaf((float)(p.y & 15), s, b);
    o0.w = fmaf((float)(p.y >> 4), s, b);
    o1.x = fmaf((float)(p.z & 15), s, b);
    o1.y = fmaf((float)(p.z >> 4), s, b);
    o1.z = fmaf((float)(p.w & 15), s, b);
    o1.w = fmaf((float)(p.w >> 4), s, b);

    long long o = (long long)j * 2;
    dst[o]     = o0;
    dst[o + 1] = o1;
}

extern "C" void kernel_launch(void* const* d_in, const int* in_sizes, int n_in,
                              void* d_out, int out_size)
{
    const int4*  kp = (const int4*) d_in[0];
    const float* ks = (const float*)d_in[1];
    const float* kb = (const float*)d_in[2];
    const int4*  vp = (const int4*) d_in[3];
    const float* vs = (const float*)d_in[4];
    const float* vb = (const float*)d_in[5];
    float4* out = (float4*)d_out;

    const int total = 2 * NVEC;                 // 2,097,152 threads
    const int tpb   = 256;
    const int blocks = total / tpb;             // 8192
    kv_dequant_kernel<<<blocks, tpb>>>(kp, ks, kb, vp, vs, vb, out);
}